// round 10
// baseline (speedup 1.0000x reference)
#include <cuda_runtime.h>
#include <math.h>

typedef unsigned long long ull;
#define BN_EPS 1e-5f

// ---------------- scratch ----------------
__device__ float g_pool[8 * 64 * 32 * 32];
__device__ float g_w2t[576 * 128];
__device__ float g_nodes0[8192 * 128];
__device__ float g_h1[8192 * 256];
__device__ float g_x1[8192 * 256];
__device__ float g_h2[8192 * 128];
__device__ float g_x2[8192 * 128];
__device__ float g_s1p[1024 * 4];
__device__ float g_d1p[1024 * 4];
__device__ float g_s2p[1024 * 2];
__device__ float g_d2p[1024 * 2];
__device__ float g_sorted[1024];
__device__ int   g_perm[1024];
__device__ float g_d[1024];
__device__ float g_smaxp[1];
__device__ float g_a[1024];
__device__ float g_b[1024];
__device__ float g_A[1024 * 256];
__device__ float g_B[1024 * 256];
__device__ float g_part[64 * 128];

// ---------------- f32x2 helpers ----------------
__device__ __forceinline__ unsigned sptr(const void* p) {
    return (unsigned)__cvta_generic_to_shared(p);
}
__device__ __forceinline__ void lds2(ull& a, ull& b, unsigned addr) {
    asm volatile("ld.shared.v2.b64 {%0,%1},[%2];" : "=l"(a), "=l"(b) : "r"(addr));
}
__device__ __forceinline__ ull dupf(float v) {
    unsigned u = __float_as_uint(v);
    ull r;
    asm("mov.b64 %0,{%1,%1};" : "=l"(r) : "r"(u));
    return r;
}
__device__ __forceinline__ void ffma2(ull& d, ull a, ull b) {
    asm("fma.rn.f32x2 %0,%1,%2,%0;" : "+l"(d) : "l"(a), "l"(b));
}
union F2U { ull u; float2 f; };
__device__ __forceinline__ float2 upk(ull u) { F2U x; x.u = u; return x.f; }

// ---------------- stage1: conv1+bn+relu+pool | w2 transpose ----------------
__global__ __launch_bounds__(256) void stage1_kernel(
    const float* __restrict__ img, const float* __restrict__ w,
    const float* __restrict__ cb, const float* __restrict__ g,
    const float* __restrict__ bb, const float* __restrict__ m,
    const float* __restrict__ v, const float* __restrict__ w2)
{
    __shared__ float ws[1728];
    __shared__ float sc_s[64], sh_s[64];
    int t = threadIdx.x;

    if (blockIdx.x >= 2048) {
        int i = (blockIdx.x - 2048) * 256 + t;      // 73728 total
        int rem = i >> 7, oc = i & 127;
        g_w2t[i] = w2[oc * 576 + rem];
        return;
    }

    for (int i = t; i < 1728; i += 256) ws[i] = w[i];
    if (t < 64) {
        float sc = g[t] * rsqrtf(v[t] + BN_EPS);
        sc_s[t] = sc;
        sh_s[t] = bb[t] - m[t] * sc + cb[t] * sc;
    }
    __syncthreads();

    int idx = blockIdx.x * 256 + t;
    int pw = idx & 31;
    int ph = (idx >> 5) & 31;
    int c  = (idx >> 10) & 63;
    int b  = idx >> 16;

    float win[3][4][4];
    int h0 = 2 * ph - 1, w0 = 2 * pw - 1;
#pragma unroll
    for (int ic = 0; ic < 3; ic++) {
        const float* ip = img + (b * 3 + ic) * 4096;
#pragma unroll
        for (int r = 0; r < 4; r++) {
            int ih = h0 + r;
            bool rok = (unsigned)ih < 64u;
#pragma unroll
            for (int cc = 0; cc < 4; cc++) {
                int iw = w0 + cc;
                win[ic][r][cc] = (rok && (unsigned)iw < 64u) ? ip[ih * 64 + iw] : 0.0f;
            }
        }
    }
    const float* wc = ws + c * 27;
    float sc = sc_s[c], sh = sh_s[c];
    float mx = 0.0f;
#pragma unroll
    for (int dh = 0; dh < 2; dh++)
#pragma unroll
    for (int dw = 0; dw < 2; dw++) {
        float s = 0.f;
#pragma unroll
        for (int ic = 0; ic < 3; ic++)
#pragma unroll
        for (int kh = 0; kh < 3; kh++)
#pragma unroll
        for (int kw = 0; kw < 3; kw++)
            s += win[ic][dh + kh][dw + kw] * wc[ic * 9 + kh * 3 + kw];
        float y = s * sc + sh;
        y = y > 0.f ? y : 0.f;
        mx = fmaxf(mx, y);
    }
    g_pool[idx] = mx;
}

// ---------------- conv2: grid (16 row-pairs, 2 oc-halves, 8 imgs) ----------------
__global__ __launch_bounds__(256) void conv2_kernel(
    const float* __restrict__ cb, const float* __restrict__ g,
    const float* __restrict__ bb, const float* __restrict__ m,
    const float* __restrict__ v)
{
    __shared__ float in_s[1088];   // 8ic x 4rows x 34cols
    __shared__ float w_s[4608];    // 72 x 64
    int t  = threadIdx.x;
    int h0 = blockIdx.x * 2;
    int oh = blockIdx.y;
    int b  = blockIdx.z;
    int px = t & 31;
    int cq = t >> 5;
    unsigned wsa = sptr(w_s);

    ull acc[2][4];
#pragma unroll
    for (int r = 0; r < 2; r++)
#pragma unroll
    for (int j = 0; j < 4; j++) acc[r][j] = 0ull;

    const float4* w2t4 = (const float4*)g_w2t;
    for (int ic0 = 0; ic0 < 64; ic0 += 8) {
        __syncthreads();
        for (int i = t; i < 1152; i += 256) {
            int rem = i >> 4, q = i & 15;
            ((float4*)w_s)[i] = w2t4[(ic0 * 9 + rem) * 32 + oh * 16 + q];
        }
        for (int i = t; i < 1088; i += 256) {
            int ic  = i / 136;
            int rem = i - ic * 136;
            int r   = rem / 34;
            int col = rem - r * 34;
            int ri = h0 - 1 + r;
            int ci = col - 1;
            float val = 0.f;
            if ((unsigned)ri < 32u && (unsigned)ci < 32u)
                val = g_pool[((b * 64 + ic0 + ic) * 32 + ri) * 32 + ci];
            in_s[i] = val;
        }
        __syncthreads();
#pragma unroll 2
        for (int ic8 = 0; ic8 < 8; ic8++) {
#pragma unroll
            for (int kr = 0; kr < 3; kr++) {
                const float* prow = in_s + (ic8 * 4 + kr) * 34 + px;
#pragma unroll
                for (int kc = 0; kc < 3; kc++) {
                    unsigned wa = wsa + (((ic8 * 9 + kr * 3 + kc) << 6) + (cq << 3)) * 4u;
                    ull w0, w1, w2x, w3;
                    lds2(w0, w1, wa);
                    lds2(w2x, w3, wa + 16);
                    ull v0 = dupf(prow[kc]);
                    ull v1 = dupf(prow[kc + 34]);
                    ffma2(acc[0][0], v0, w0);  ffma2(acc[0][1], v0, w1);
                    ffma2(acc[0][2], v0, w2x); ffma2(acc[0][3], v0, w3);
                    ffma2(acc[1][0], v1, w0);  ffma2(acc[1][1], v1, w1);
                    ffma2(acc[1][2], v1, w2x); ffma2(acc[1][3], v1, w3);
                }
            }
        }
    }

    int cbase = oh * 64 + cq * 8;
    float scs[8], shs[8];
#pragma unroll
    for (int j = 0; j < 8; j++) {
        int c = cbase + j;
        float sc = g[c] * rsqrtf(v[c] + BN_EPS);
        scs[j] = sc;
        shs[j] = bb[c] - m[c] * sc + cb[c] * sc;
    }
#pragma unroll
    for (int r = 0; r < 2; r++) {
        int node = b * 1024 + (h0 + r) * 32 + px;
        float* op = g_nodes0 + node * 128 + cbase;
        float outv[8];
#pragma unroll
        for (int jp = 0; jp < 4; jp++) {
            float2 p = upk(acc[r][jp]);
            outv[2 * jp]     = p.x;
            outv[2 * jp + 1] = p.y;
        }
#pragma unroll
        for (int j = 0; j < 8; j++) {
            float y = outv[j] * scs[j] + shs[j];
            outv[j] = y > 0.f ? y : 0.f;
        }
        *(float4*)op       = *(float4*)&outv[0];
        *(float4*)(op + 4) = *(float4*)&outv[4];
    }
}

// ---------------- SGEMM: 128x64 tile, 8x4/thread, double-buffered, fused epilogue ----------------
__global__ __launch_bounds__(256) void sgemm_fused(
    const float* __restrict__ A, const float* __restrict__ B,
    const float* __restrict__ bias, const float* __restrict__ asrc,
    const float* __restrict__ adst, float* __restrict__ H,
    float* __restrict__ X, float* __restrict__ s_part,
    float* __restrict__ d_part, int N, int K)
{
    __shared__ float As[2][16][128];
    __shared__ float Bs[2][16][64];
    int t = threadIdx.x;
    int bm = blockIdx.y * 128, bn = blockIdx.x * 64;
    int tx = t & 15, ty = t >> 4;
    int ar = t >> 1, a8 = (t & 1) * 8;
    int bk = t >> 4, bc = (t & 15) * 4;
    const float* Aload = A + (size_t)(bm + ar) * K + a8;
    const float* Bload = B + (size_t)bk * N + bn + bc;
    unsigned bsB = sptr(Bs);

    float4 pa0 = *(const float4*)(Aload);
    float4 pa1 = *(const float4*)(Aload + 4);
    float4 pb  = *(const float4*)(Bload);

    ull acc[8][2];
#pragma unroll
    for (int i = 0; i < 8; i++) { acc[i][0] = 0ull; acc[i][1] = 0ull; }

    int NC = K >> 4;
    for (int ch = 0; ch < NC; ch++) {
        int p = ch & 1;
        As[p][a8 + 0][ar] = pa0.x; As[p][a8 + 1][ar] = pa0.y;
        As[p][a8 + 2][ar] = pa0.z; As[p][a8 + 3][ar] = pa0.w;
        As[p][a8 + 4][ar] = pa1.x; As[p][a8 + 5][ar] = pa1.y;
        As[p][a8 + 6][ar] = pa1.z; As[p][a8 + 7][ar] = pa1.w;
        *(float4*)&Bs[p][bk][bc] = pb;
        __syncthreads();
        if (ch + 1 < NC) {
            pa0 = *(const float4*)(Aload + (ch + 1) * 16);
            pa1 = *(const float4*)(Aload + (ch + 1) * 16 + 4);
            pb  = *(const float4*)(Bload + (size_t)(ch + 1) * 16 * N);
        }
        unsigned bbase = bsB + (unsigned)p * 4096u + (unsigned)tx * 16u;
#pragma unroll
        for (int k = 0; k < 16; k++) {
            float4 a0 = *(const float4*)&As[p][k][ty * 8];
            float4 a1 = *(const float4*)&As[p][k][ty * 8 + 4];
            ull b01, b23;
            lds2(b01, b23, bbase + (unsigned)k * 256u);
            ull d;
            d = dupf(a0.x); ffma2(acc[0][0], d, b01); ffma2(acc[0][1], d, b23);
            d = dupf(a0.y); ffma2(acc[1][0], d, b01); ffma2(acc[1][1], d, b23);
            d = dupf(a0.z); ffma2(acc[2][0], d, b01); ffma2(acc[2][1], d, b23);
            d = dupf(a0.w); ffma2(acc[3][0], d, b01); ffma2(acc[3][1], d, b23);
            d = dupf(a1.x); ffma2(acc[4][0], d, b01); ffma2(acc[4][1], d, b23);
            d = dupf(a1.y); ffma2(acc[5][0], d, b01); ffma2(acc[5][1], d, b23);
            d = dupf(a1.z); ffma2(acc[6][0], d, b01); ffma2(acc[6][1], d, b23);
            d = dupf(a1.w); ffma2(acc[7][0], d, b01); ffma2(acc[7][1], d, b23);
        }
    }

    float c[8][4];
#pragma unroll
    for (int rr = 0; rr < 8; rr++) {
        float2 lo = upk(acc[rr][0]);
        float2 hi = upk(acc[rr][1]);
        c[rr][0] = lo.x; c[rr][1] = lo.y; c[rr][2] = hi.x; c[rr][3] = hi.y;
    }
    int col = bn + tx * 4;

    if (bm >= 1024) {
        float4 bv = *(const float4*)&bias[col];
#pragma unroll
        for (int rr = 0; rr < 8; rr++) {
            float y0 = c[rr][0] + bv.x; y0 = y0 > 0.f ? y0 : 0.f;
            float y1 = c[rr][1] + bv.y; y1 = y1 > 0.f ? y1 : 0.f;
            float y2 = c[rr][2] + bv.z; y2 = y2 > 0.f ? y2 : 0.f;
            float y3 = c[rr][3] + bv.w; y3 = y3 > 0.f ? y3 : 0.f;
            *(float4*)&X[(size_t)(bm + ty * 8 + rr) * N + col] =
                make_float4(y0, y1, y2, y3);
        }
    } else {
        float4 av = *(const float4*)&asrc[col];
        float4 dv = *(const float4*)&adst[col];
        int NB = gridDim.x;
#pragma unroll
        for (int rr = 0; rr < 8; rr++) {
            *(float4*)&H[(size_t)(bm + ty * 8 + rr) * N + col] =
                make_float4(c[rr][0], c[rr][1], c[rr][2], c[rr][3]);
            float sp = c[rr][0] * av.x + c[rr][1] * av.y + c[rr][2] * av.z + c[rr][3] * av.w;
            float dp = c[rr][0] * dv.x + c[rr][1] * dv.y + c[rr][2] * dv.z + c[rr][3] * dv.w;
#pragma unroll
            for (int off = 8; off > 0; off >>= 1) {
                sp += __shfl_xor_sync(0xffffffffu, sp, off);
                dp += __shfl_xor_sync(0xffffffffu, dp, off);
            }
            if ((t & 15) == 0) {
                int row = bm + ty * 8 + rr;
                s_part[row * NB + blockIdx.x] = sp;
                d_part[row * NB + blockIdx.x] = dp;
            }
        }
    }
}

// ---------------- attention v6 stage A: combine partials, rank-sort s, smax, d ----------------
// grid 16 x 64 threads; block handles ranks for i in [blk*64, blk*64+64)
template <int NB>
__global__ __launch_bounds__(64) void sortprep_kernel(
    const float* __restrict__ s_part, const float* __restrict__ d_part)
{
    __shared__ float s_all[1024];
    __shared__ float wm[2];
    int t = threadIdx.x;
    int blk = blockIdx.x;

    float lmax = -1e30f;
    for (int idx = t; idx < 1024; idx += 64) {
        float s = 0.f;
#pragma unroll
        for (int nb = 0; nb < NB; nb++) s += s_part[idx * NB + nb];
        s_all[idx] = s;
        lmax = fmaxf(lmax, s);
    }
#pragma unroll
    for (int o = 16; o > 0; o >>= 1)
        lmax = fmaxf(lmax, __shfl_xor_sync(0xffffffffu, lmax, o));
    if ((t & 31) == 0) wm[t >> 5] = lmax;
    __syncthreads();

    int i = blk * 64 + t;
    float si = s_all[i];
    int rank = 0;
#pragma unroll 4
    for (int i2 = 0; i2 < 1024; i2++) {
        float v = s_all[i2];
        rank += (v < si) || (v == si && i2 < i);
    }
    g_sorted[rank] = si;
    g_perm[rank] = i;

    if (blk == 0) {
        for (int idx = t; idx < 1024; idx += 64) {
            float d = 0.f;
#pragma unroll
            for (int nb = 0; nb < NB; nb++) d += d_part[idx * NB + nb];
            g_d[idx] = d;
        }
        if (t == 0) g_smaxp[0] = fmaxf(wm[0], wm[1]);
    }
}

// ---------------- attention v6 stage B: chunked prefix scans ----------------
// grid 16 (chunks of 64 sorted rows) x D threads. Inclusive local prefixes of
// wA*h and wB*h plus scalar prefixes (thread 0).
template <int D>
__global__ __launch_bounds__(D) void scan_kernel(const float* __restrict__ h)
{
    __shared__ int perm_s[64];
    __shared__ float wA_s[64], wB_s[64];
    int t = threadIdx.x;
    int c = blockIdx.x;
    float smax = g_smaxp[0];

    if (t < 64) {
        int pos = c * 64 + t;
        perm_s[t] = g_perm[pos];
        float sv = g_sorted[pos];
        wA_s[t] = __expf(0.2f * (sv - smax));
        wB_s[t] = __expf(sv - smax);
    }
    __syncthreads();

    float accA = 0.f, accB = 0.f;
#pragma unroll 4
    for (int k = 0; k < 64; k++) {
        int i = perm_s[k];
        float hv = h[(size_t)i * D + t];
        accA += wA_s[k] * hv;
        accB += wB_s[k] * hv;
        int pos = c * 64 + k;
        g_A[(size_t)pos * D + t] = accA;
        g_B[(size_t)pos * D + t] = accB;
    }
    if (t == 0) {
        float sa = 0.f, sb = 0.f;
        for (int k = 0; k < 64; k++) {
            sa += wA_s[k];
            sb += wB_s[k];
            g_a[c * 64 + k] = sa;
            g_b[c * 64 + k] = sb;
        }
    }
}

// ---------------- attention v6 stage C: per-j combine via threshold lookup ----------------
// out_j = (fA*A(k_j) + fB*(Btot - Bpre(k_j))) / den_j + bias, relu
// grid 64 blocks x 256 threads; 16 j per block.
template <int D>
__global__ __launch_bounds__(256) void attn_combine(
    const float* __restrict__ bias, float* __restrict__ out)
{
    __shared__ float sorted_s[1024];
    __shared__ float offA[17 * D], offB[17 * D];
    __shared__ float offa[17], offb[17];
    __shared__ int   ks_s[16];
    __shared__ float fA_s[16], fB_s[16], inv_s[16];
    int t = threadIdx.x;
    int j0 = blockIdx.x * 16;

    for (int idx = t; idx < 1024; idx += 256) sorted_s[idx] = g_sorted[idx];

    if (t < D) {
        float aA = 0.f, aB = 0.f;
        offA[t] = 0.f; offB[t] = 0.f;
#pragma unroll
        for (int c = 0; c < 16; c++) {
            aA += g_A[(size_t)(c * 64 + 63) * D + t];
            aB += g_B[(size_t)(c * 64 + 63) * D + t];
            offA[(c + 1) * D + t] = aA;
            offB[(c + 1) * D + t] = aB;
        }
    }
    if (t == 0) {
        float aa = 0.f, bb = 0.f;
        offa[0] = 0.f; offb[0] = 0.f;
#pragma unroll
        for (int c = 0; c < 16; c++) {
            aa += g_a[c * 64 + 63];
            bb += g_b[c * 64 + 63];
            offa[c + 1] = aa;
            offb[c + 1] = bb;
        }
    }
    __syncthreads();

    if (t < 16) {
        int j = j0 + t;
        float dj = g_d[j];
        float smax = g_smaxp[0];
        float x = -dj;
        int lo = 0, hi = 1024;
        while (lo < hi) {
            int mid = (lo + hi) >> 1;
            if (sorted_s[mid] <= x) lo = mid + 1; else hi = mid;
        }
        int k = lo;                 // count of s_i <= -d_j
        ks_s[t] = k;
        float tt = smax + dj;
        float mj = tt > 0.f ? tt : 0.2f * tt;
        float fB = __expf(tt - mj);
        float fA = __expf(0.2f * tt - mj);
        float av = 0.f, bv = 0.f;
        if (k > 0) {
            int p = k - 1;
            av = offa[p >> 6] + g_a[p];
            bv = offb[p >> 6] + g_b[p];
        }
        float btot = offb[16];
        float den = fA * av + fB * (btot - bv);
        fA_s[t] = fA;
        fB_s[t] = fB;
        inv_s[t] = 1.0f / den;
    }
    __syncthreads();

    const int ITER = 16 * D / 256;
#pragma unroll
    for (int it = 0; it < ITER; it++) {
        int o = t + it * 256;
        int jj = o / D, f = o % D;
        int k = ks_s[jj];
        float Av = 0.f, Bpre = 0.f;
        if (k > 0) {
            int p = k - 1;
            int ch = p >> 6;
            Av   = offA[ch * D + f] + g_A[(size_t)p * D + f];
            Bpre = offB[ch * D + f] + g_B[(size_t)p * D + f];
        }
        float Btot = offB[16 * D + f];
        float num = fA_s[jj] * Av + fB_s[jj] * (Btot - Bpre);
        float y = num * inv_s[jj] + bias[f];
        out[(size_t)(j0 + jj) * D + f] = y > 0.f ? y : 0.f;
    }
}

// ---------------- mean pool stage 1 ----------------
__global__ __launch_bounds__(128) void pool_partial_kernel()
{
    int b = blockIdx.x >> 3, ch = blockIdx.x & 7, t = threadIdx.x;
    const float* base = g_x2 + (b * 1024 + ch * 128) * 128;
    float acc = 0.f;
    for (int n = 0; n < 128; n++) acc += base[n * 128 + t];
    g_part[blockIdx.x * 128 + t] = acc;
}

// ---------------- stage 2: combine + linear + log_softmax ----------------
__global__ __launch_bounds__(128) void final_kernel(
    const float* __restrict__ W, const float* __restrict__ bo,
    float* __restrict__ out)
{
    __shared__ float meanv[128];
    __shared__ float logits[10];
    __shared__ float stats[2];
    int b = blockIdx.x;
    int t = threadIdx.x;
    float acc = 0.f;
#pragma unroll
    for (int k = 0; k < 8; k++) acc += g_part[(b * 8 + k) * 128 + t];
    meanv[t] = acc * (1.0f / 1024.0f);
    __syncthreads();
    if (t < 10) {
        float lg = bo[t];
        for (int f = 0; f < 128; f++) lg += meanv[f] * W[f * 10 + t];
        logits[t] = lg;
    }
    __syncthreads();
    if (t == 0) {
        float mv = -1e30f;
        for (int k = 0; k < 10; k++) mv = fmaxf(mv, logits[k]);
        float se = 0.f;
        for (int k = 0; k < 10; k++) se += expf(logits[k] - mv);
        stats[0] = mv;
        stats[1] = logf(se);
    }
    __syncthreads();
    if (t < 10) out[b * 10 + t] = logits[t] - stats[0] - stats[1];
}

// ---------------- launch ----------------
extern "C" void kernel_launch(void* const* d_in, const int* in_sizes, int n_in,
                              void* d_out, int out_size)
{
    const float* images  = (const float*)d_in[0];
    const float* conv1_w = (const float*)d_in[1];
    const float* conv1_b = (const float*)d_in[2];
    const float* bn1_g   = (const float*)d_in[3];
    const float* bn1_b   = (const float*)d_in[4];
    const float* bn1_m   = (const float*)d_in[5];
    const float* bn1_v   = (const float*)d_in[6];
    const float* conv2_w = (const float*)d_in[7];
    const float* conv2_b = (const float*)d_in[8];
    const float* bn2_g   = (const float*)d_in[9];
    const float* bn2_b   = (const float*)d_in[10];
    const float* bn2_m   = (const float*)d_in[11];
    const float* bn2_v   = (const float*)d_in[12];
    const float* gat1_w    = (const float*)d_in[13];
    const float* gat1_asrc = (const float*)d_in[14];
    const float* gat1_adst = (const float*)d_in[15];
    const float* gat1_bias = (const float*)d_in[16];
    const float* gat2_w    = (const float*)d_in[17];
    const float* gat2_asrc = (const float*)d_in[18];
    const float* gat2_adst = (const float*)d_in[19];
    const float* gat2_bias = (const float*)d_in[20];
    const float* out_w = (const float*)d_in[21];
    const float* out_b = (const float*)d_in[22];
    float* out = (float*)d_out;

    float* nodes0 = nullptr; cudaGetSymbolAddress((void**)&nodes0, g_nodes0);
    float* h1 = nullptr;     cudaGetSymbolAddress((void**)&h1, g_h1);
    float* x1 = nullptr;     cudaGetSymbolAddress((void**)&x1, g_x1);
    float* h2 = nullptr;     cudaGetSymbolAddress((void**)&h2, g_h2);
    float* x2 = nullptr;     cudaGetSymbolAddress((void**)&x2, g_x2);
    float* s1p = nullptr;    cudaGetSymbolAddress((void**)&s1p, g_s1p);
    float* d1p = nullptr;    cudaGetSymbolAddress((void**)&d1p, g_d1p);
    float* s2p = nullptr;    cudaGetSymbolAddress((void**)&s2p, g_s2p);
    float* d2p = nullptr;    cudaGetSymbolAddress((void**)&d2p, g_d2p);

    stage1_kernel<<<2048 + 288, 256>>>(images, conv1_w, conv1_b, bn1_g, bn1_b,
                                       bn1_m, bn1_v, conv2_w);
    conv2_kernel<<<dim3(16, 2, 8), 256>>>(conv2_b, bn2_g, bn2_b, bn2_m, bn2_v);

    // GAT layer 1
    sgemm_fused<<<dim3(4, 64), 256>>>(nodes0, gat1_w, gat1_bias, gat1_asrc,
                                      gat1_adst, h1, x1, s1p, d1p, 256, 128);
    sortprep_kernel<4><<<16, 64>>>(s1p, d1p);
    scan_kernel<256><<<16, 256>>>(h1);
    attn_combine<256><<<64, 256>>>(gat1_bias, x1);

    // GAT layer 2
    sgemm_fused<<<dim3(2, 64), 256>>>(x1, gat2_w, gat2_bias, gat2_asrc,
                                      gat2_adst, h2, x2, s2p, d2p, 128, 256);
    sortprep_kernel<2><<<16, 64>>>(s2p, d2p);
    scan_kernel<128><<<16, 128>>>(h2);
    attn_combine<128><<<64, 256>>>(gat2_bias, x2);

    pool_partial_kernel<<<64, 128>>>();
    final_kernel<<<8, 128>>>(out_w, out_b, out);
}

// round 11
// speedup vs baseline: 1.2196x; 1.2196x over previous
#include <cuda_runtime.h>
#include <math.h>

typedef unsigned long long ull;
#define BN_EPS 1e-5f

// ---------------- scratch ----------------
__device__ float g_pool[8 * 64 * 32 * 32];
__device__ float g_w2t[576 * 128];
__device__ float g_nodes0[8192 * 128];
__device__ float g_h1[8192 * 256];
__device__ float g_x1[8192 * 256];
__device__ float g_h2[8192 * 128];
__device__ float g_x2[8192 * 128];
__device__ float g_s1p[1024 * 4];
__device__ float g_d1p[1024 * 4];
__device__ float g_s2p[1024 * 2];
__device__ float g_d2p[1024 * 2];
__device__ float g_sorted[1024];
__device__ int   g_perm[1024];
__device__ float g_d[1024];
__device__ float g_smaxp[1];
__device__ float g_a[1024];
__device__ float g_b[1024];
__device__ float g_A[1024 * 256];
__device__ float g_B[1024 * 256];
__device__ float g_part[64 * 128];

// ---------------- f32x2 helpers ----------------
__device__ __forceinline__ unsigned sptr(const void* p) {
    return (unsigned)__cvta_generic_to_shared(p);
}
__device__ __forceinline__ void lds2(ull& a, ull& b, unsigned addr) {
    asm volatile("ld.shared.v2.b64 {%0,%1},[%2];" : "=l"(a), "=l"(b) : "r"(addr));
}
__device__ __forceinline__ ull dupf(float v) {
    unsigned u = __float_as_uint(v);
    ull r;
    asm("mov.b64 %0,{%1,%1};" : "=l"(r) : "r"(u));
    return r;
}
__device__ __forceinline__ void ffma2(ull& d, ull a, ull b) {
    asm("fma.rn.f32x2 %0,%1,%2,%0;" : "+l"(d) : "l"(a), "l"(b));
}
union F2U { ull u; float2 f; };
__device__ __forceinline__ float2 upk(ull u) { F2U x; x.u = u; return x.f; }

// ---------------- stage1: conv1+bn+relu+pool | w2 transpose ----------------
__global__ __launch_bounds__(256) void stage1_kernel(
    const float* __restrict__ img, const float* __restrict__ w,
    const float* __restrict__ cb, const float* __restrict__ g,
    const float* __restrict__ bb, const float* __restrict__ m,
    const float* __restrict__ v, const float* __restrict__ w2)
{
    __shared__ float ws[1728];
    __shared__ float sc_s[64], sh_s[64];
    int t = threadIdx.x;

    if (blockIdx.x >= 2048) {
        int i = (blockIdx.x - 2048) * 256 + t;      // 73728 total
        int rem = i >> 7, oc = i & 127;
        g_w2t[i] = w2[oc * 576 + rem];
        return;
    }

    for (int i = t; i < 1728; i += 256) ws[i] = w[i];
    if (t < 64) {
        float sc = g[t] * rsqrtf(v[t] + BN_EPS);
        sc_s[t] = sc;
        sh_s[t] = bb[t] - m[t] * sc + cb[t] * sc;
    }
    __syncthreads();

    int idx = blockIdx.x * 256 + t;
    int pw = idx & 31;
    int ph = (idx >> 5) & 31;
    int c  = (idx >> 10) & 63;
    int b  = idx >> 16;

    float win[3][4][4];
    int h0 = 2 * ph - 1, w0 = 2 * pw - 1;
#pragma unroll
    for (int ic = 0; ic < 3; ic++) {
        const float* ip = img + (b * 3 + ic) * 4096;
#pragma unroll
        for (int r = 0; r < 4; r++) {
            int ih = h0 + r;
            bool rok = (unsigned)ih < 64u;
#pragma unroll
            for (int cc = 0; cc < 4; cc++) {
                int iw = w0 + cc;
                win[ic][r][cc] = (rok && (unsigned)iw < 64u) ? ip[ih * 64 + iw] : 0.0f;
            }
        }
    }
    const float* wc = ws + c * 27;
    float sc = sc_s[c], sh = sh_s[c];
    float mx = 0.0f;
#pragma unroll
    for (int dh = 0; dh < 2; dh++)
#pragma unroll
    for (int dw = 0; dw < 2; dw++) {
        float s = 0.f;
#pragma unroll
        for (int ic = 0; ic < 3; ic++)
#pragma unroll
        for (int kh = 0; kh < 3; kh++)
#pragma unroll
        for (int kw = 0; kw < 3; kw++)
            s += win[ic][dh + kh][dw + kw] * wc[ic * 9 + kh * 3 + kw];
        float y = s * sc + sh;
        y = y > 0.f ? y : 0.f;
        mx = fmaxf(mx, y);
    }
    g_pool[idx] = mx;
}

// ---------------- conv2: grid (16 row-pairs, 2 oc-halves, 8 imgs) ----------------
__global__ __launch_bounds__(256) void conv2_kernel(
    const float* __restrict__ cb, const float* __restrict__ g,
    const float* __restrict__ bb, const float* __restrict__ m,
    const float* __restrict__ v)
{
    __shared__ float in_s[1088];   // 8ic x 4rows x 34cols
    __shared__ float w_s[4608];    // 72 x 64
    int t  = threadIdx.x;
    int h0 = blockIdx.x * 2;
    int oh = blockIdx.y;
    int b  = blockIdx.z;
    int px = t & 31;
    int cq = t >> 5;
    unsigned wsa = sptr(w_s);

    ull acc[2][4];
#pragma unroll
    for (int r = 0; r < 2; r++)
#pragma unroll
    for (int j = 0; j < 4; j++) acc[r][j] = 0ull;

    const float4* w2t4 = (const float4*)g_w2t;
    for (int ic0 = 0; ic0 < 64; ic0 += 8) {
        __syncthreads();
        for (int i = t; i < 1152; i += 256) {
            int rem = i >> 4, q = i & 15;
            ((float4*)w_s)[i] = w2t4[(ic0 * 9 + rem) * 32 + oh * 16 + q];
        }
        for (int i = t; i < 1088; i += 256) {
            int ic  = i / 136;
            int rem = i - ic * 136;
            int r   = rem / 34;
            int col = rem - r * 34;
            int ri = h0 - 1 + r;
            int ci = col - 1;
            float val = 0.f;
            if ((unsigned)ri < 32u && (unsigned)ci < 32u)
                val = g_pool[((b * 64 + ic0 + ic) * 32 + ri) * 32 + ci];
            in_s[i] = val;
        }
        __syncthreads();
#pragma unroll 2
        for (int ic8 = 0; ic8 < 8; ic8++) {
#pragma unroll
            for (int kr = 0; kr < 3; kr++) {
                const float* prow = in_s + (ic8 * 4 + kr) * 34 + px;
#pragma unroll
                for (int kc = 0; kc < 3; kc++) {
                    unsigned wa = wsa + (((ic8 * 9 + kr * 3 + kc) << 6) + (cq << 3)) * 4u;
                    ull w0, w1, w2x, w3;
                    lds2(w0, w1, wa);
                    lds2(w2x, w3, wa + 16);
                    ull v0 = dupf(prow[kc]);
                    ull v1 = dupf(prow[kc + 34]);
                    ffma2(acc[0][0], v0, w0);  ffma2(acc[0][1], v0, w1);
                    ffma2(acc[0][2], v0, w2x); ffma2(acc[0][3], v0, w3);
                    ffma2(acc[1][0], v1, w0);  ffma2(acc[1][1], v1, w1);
                    ffma2(acc[1][2], v1, w2x); ffma2(acc[1][3], v1, w3);
                }
            }
        }
    }

    int cbase = oh * 64 + cq * 8;
    float scs[8], shs[8];
#pragma unroll
    for (int j = 0; j < 8; j++) {
        int c = cbase + j;
        float sc = g[c] * rsqrtf(v[c] + BN_EPS);
        scs[j] = sc;
        shs[j] = bb[c] - m[c] * sc + cb[c] * sc;
    }
#pragma unroll
    for (int r = 0; r < 2; r++) {
        int node = b * 1024 + (h0 + r) * 32 + px;
        float* op = g_nodes0 + node * 128 + cbase;
        float outv[8];
#pragma unroll
        for (int jp = 0; jp < 4; jp++) {
            float2 p = upk(acc[r][jp]);
            outv[2 * jp]     = p.x;
            outv[2 * jp + 1] = p.y;
        }
#pragma unroll
        for (int j = 0; j < 8; j++) {
            float y = outv[j] * scs[j] + shs[j];
            outv[j] = y > 0.f ? y : 0.f;
        }
        *(float4*)op       = *(float4*)&outv[0];
        *(float4*)(op + 4) = *(float4*)&outv[4];
    }
}

// ---------------- SGEMM: 128x64 tile, 8x4/thread, double-buffered, fused epilogue ----------------
__global__ __launch_bounds__(256) void sgemm_fused(
    const float* __restrict__ A, const float* __restrict__ B,
    const float* __restrict__ bias, const float* __restrict__ asrc,
    const float* __restrict__ adst, float* __restrict__ H,
    float* __restrict__ X, float* __restrict__ s_part,
    float* __restrict__ d_part, int N, int K)
{
    __shared__ float As[2][16][128];
    __shared__ float Bs[2][16][64];
    int t = threadIdx.x;
    int bm = blockIdx.y * 128, bn = blockIdx.x * 64;
    int tx = t & 15, ty = t >> 4;
    int ar = t >> 1, a8 = (t & 1) * 8;
    int bk = t >> 4, bc = (t & 15) * 4;
    const float* Aload = A + (size_t)(bm + ar) * K + a8;
    const float* Bload = B + (size_t)bk * N + bn + bc;
    unsigned bsB = sptr(Bs);

    float4 pa0 = *(const float4*)(Aload);
    float4 pa1 = *(const float4*)(Aload + 4);
    float4 pb  = *(const float4*)(Bload);

    ull acc[8][2];
#pragma unroll
    for (int i = 0; i < 8; i++) { acc[i][0] = 0ull; acc[i][1] = 0ull; }

    int NC = K >> 4;
    for (int ch = 0; ch < NC; ch++) {
        int p = ch & 1;
        As[p][a8 + 0][ar] = pa0.x; As[p][a8 + 1][ar] = pa0.y;
        As[p][a8 + 2][ar] = pa0.z; As[p][a8 + 3][ar] = pa0.w;
        As[p][a8 + 4][ar] = pa1.x; As[p][a8 + 5][ar] = pa1.y;
        As[p][a8 + 6][ar] = pa1.z; As[p][a8 + 7][ar] = pa1.w;
        *(float4*)&Bs[p][bk][bc] = pb;
        __syncthreads();
        if (ch + 1 < NC) {
            pa0 = *(const float4*)(Aload + (ch + 1) * 16);
            pa1 = *(const float4*)(Aload + (ch + 1) * 16 + 4);
            pb  = *(const float4*)(Bload + (size_t)(ch + 1) * 16 * N);
        }
        unsigned bbase = bsB + (unsigned)p * 4096u + (unsigned)tx * 16u;
#pragma unroll
        for (int k = 0; k < 16; k++) {
            float4 a0 = *(const float4*)&As[p][k][ty * 8];
            float4 a1 = *(const float4*)&As[p][k][ty * 8 + 4];
            ull b01, b23;
            lds2(b01, b23, bbase + (unsigned)k * 256u);
            ull d;
            d = dupf(a0.x); ffma2(acc[0][0], d, b01); ffma2(acc[0][1], d, b23);
            d = dupf(a0.y); ffma2(acc[1][0], d, b01); ffma2(acc[1][1], d, b23);
            d = dupf(a0.z); ffma2(acc[2][0], d, b01); ffma2(acc[2][1], d, b23);
            d = dupf(a0.w); ffma2(acc[3][0], d, b01); ffma2(acc[3][1], d, b23);
            d = dupf(a1.x); ffma2(acc[4][0], d, b01); ffma2(acc[4][1], d, b23);
            d = dupf(a1.y); ffma2(acc[5][0], d, b01); ffma2(acc[5][1], d, b23);
            d = dupf(a1.z); ffma2(acc[6][0], d, b01); ffma2(acc[6][1], d, b23);
            d = dupf(a1.w); ffma2(acc[7][0], d, b01); ffma2(acc[7][1], d, b23);
        }
    }

    float c[8][4];
#pragma unroll
    for (int rr = 0; rr < 8; rr++) {
        float2 lo = upk(acc[rr][0]);
        float2 hi = upk(acc[rr][1]);
        c[rr][0] = lo.x; c[rr][1] = lo.y; c[rr][2] = hi.x; c[rr][3] = hi.y;
    }
    int col = bn + tx * 4;

    if (bm >= 1024) {
        float4 bv = *(const float4*)&bias[col];
#pragma unroll
        for (int rr = 0; rr < 8; rr++) {
            float y0 = c[rr][0] + bv.x; y0 = y0 > 0.f ? y0 : 0.f;
            float y1 = c[rr][1] + bv.y; y1 = y1 > 0.f ? y1 : 0.f;
            float y2 = c[rr][2] + bv.z; y2 = y2 > 0.f ? y2 : 0.f;
            float y3 = c[rr][3] + bv.w; y3 = y3 > 0.f ? y3 : 0.f;
            *(float4*)&X[(size_t)(bm + ty * 8 + rr) * N + col] =
                make_float4(y0, y1, y2, y3);
        }
    } else {
        float4 av = *(const float4*)&asrc[col];
        float4 dv = *(const float4*)&adst[col];
        int NB = gridDim.x;
#pragma unroll
        for (int rr = 0; rr < 8; rr++) {
            *(float4*)&H[(size_t)(bm + ty * 8 + rr) * N + col] =
                make_float4(c[rr][0], c[rr][1], c[rr][2], c[rr][3]);
            float sp = c[rr][0] * av.x + c[rr][1] * av.y + c[rr][2] * av.z + c[rr][3] * av.w;
            float dp = c[rr][0] * dv.x + c[rr][1] * dv.y + c[rr][2] * dv.z + c[rr][3] * dv.w;
#pragma unroll
            for (int off = 8; off > 0; off >>= 1) {
                sp += __shfl_xor_sync(0xffffffffu, sp, off);
                dp += __shfl_xor_sync(0xffffffffu, dp, off);
            }
            if ((t & 15) == 0) {
                int row = bm + ty * 8 + rr;
                s_part[row * NB + blockIdx.x] = sp;
                d_part[row * NB + blockIdx.x] = dp;
            }
        }
    }
}

// ---------------- attention stage A v2: rank-sort, one warp per node ----------------
// grid 128 x 256 threads; warp w of block b ranks node i = b*8 + w.
template <int NB>
__global__ __launch_bounds__(256) void sortprep_kernel(
    const float* __restrict__ s_part, const float* __restrict__ d_part)
{
    __shared__ float s_all[1024];
    __shared__ float wred[8];
    int t = threadIdx.x;
    int blk = blockIdx.x;

    for (int idx = t; idx < 1024; idx += 256) {
        float s = 0.f;
#pragma unroll
        for (int nb = 0; nb < NB; nb++) s += s_part[idx * NB + nb];
        s_all[idx] = s;
    }
    __syncthreads();

    int w = t >> 5, lane = t & 31;
    int i = blk * 8 + w;
    float si = s_all[i];
    int cnt = 0;
#pragma unroll 8
    for (int k = lane; k < 1024; k += 32) {
        float v = s_all[k];
        cnt += (v < si) || (v == si && k < i);
    }
#pragma unroll
    for (int o = 16; o > 0; o >>= 1)
        cnt += __shfl_xor_sync(0xffffffffu, cnt, o);
    if (lane == 0) { g_sorted[cnt] = si; g_perm[cnt] = i; }

    if (blk == 0) {
        for (int idx = t; idx < 1024; idx += 256) {
            float d = 0.f;
#pragma unroll
            for (int nb = 0; nb < NB; nb++) d += d_part[idx * NB + nb];
            g_d[idx] = d;
        }
        float lmax = -1e30f;
        for (int idx = t; idx < 1024; idx += 256)
            lmax = fmaxf(lmax, s_all[idx]);
#pragma unroll
        for (int o = 16; o > 0; o >>= 1)
            lmax = fmaxf(lmax, __shfl_xor_sync(0xffffffffu, lmax, o));
        if (lane == 0) wred[w] = lmax;
        __syncthreads();
        if (t == 0) {
            float mv = wred[0];
#pragma unroll
            for (int k = 1; k < 8; k++) mv = fmaxf(mv, wred[k]);
            g_smaxp[0] = mv;
        }
    }
}

// ---------------- attention stage B v2: chunked prefix scans, feature-sliced ----------------
// grid (16 chunks, D/64 slices) x 64 threads. Inclusive local prefixes of
// wA*h and wB*h; scalar prefixes by (c, slice 0) thread 0.
template <int D>
__global__ __launch_bounds__(64) void scan_kernel(const float* __restrict__ h)
{
    __shared__ int perm_s[64];
    __shared__ float wA_s[64], wB_s[64];
    int t = threadIdx.x;
    int c = blockIdx.x;
    int f = blockIdx.y * 64 + t;
    float smax = g_smaxp[0];

    {
        int pos = c * 64 + t;
        perm_s[t] = g_perm[pos];
        float sv = g_sorted[pos];
        wA_s[t] = __expf(0.2f * (sv - smax));
        wB_s[t] = __expf(sv - smax);
    }
    __syncthreads();

    float accA = 0.f, accB = 0.f;
#pragma unroll 8
    for (int k = 0; k < 64; k++) {
        float hv = h[(size_t)perm_s[k] * D + f];
        accA += wA_s[k] * hv;
        accB += wB_s[k] * hv;
        int pos = c * 64 + k;
        g_A[(size_t)pos * D + f] = accA;
        g_B[(size_t)pos * D + f] = accB;
    }
    if (blockIdx.y == 0 && t == 0) {
        float sa = 0.f, sb = 0.f;
        for (int k = 0; k < 64; k++) {
            sa += wA_s[k];
            sb += wB_s[k];
            g_a[c * 64 + k] = sa;
            g_b[c * 64 + k] = sb;
        }
    }
}

// ---------------- attention stage C: per-j combine via threshold lookup ----------------
// out_j = (fA*A(k_j) + fB*(Btot - Bpre(k_j))) / den_j + bias, relu
// grid 64 blocks x 256 threads; 16 j per block.
template <int D>
__global__ __launch_bounds__(256) void attn_combine(
    const float* __restrict__ bias, float* __restrict__ out)
{
    __shared__ float sorted_s[1024];
    __shared__ float offA[17 * D], offB[17 * D];
    __shared__ float offa[17], offb[17];
    __shared__ int   ks_s[16];
    __shared__ float fA_s[16], fB_s[16], inv_s[16];
    int t = threadIdx.x;
    int j0 = blockIdx.x * 16;

    for (int idx = t; idx < 1024; idx += 256) sorted_s[idx] = g_sorted[idx];

    if (t < D) {
        float aA = 0.f, aB = 0.f;
        offA[t] = 0.f; offB[t] = 0.f;
#pragma unroll
        for (int c = 0; c < 16; c++) {
            aA += g_A[(size_t)(c * 64 + 63) * D + t];
            aB += g_B[(size_t)(c * 64 + 63) * D + t];
            offA[(c + 1) * D + t] = aA;
            offB[(c + 1) * D + t] = aB;
        }
    }
    if (t == 0) {
        float aa = 0.f, bb = 0.f;
        offa[0] = 0.f; offb[0] = 0.f;
#pragma unroll
        for (int c = 0; c < 16; c++) {
            aa += g_a[c * 64 + 63];
            bb += g_b[c * 64 + 63];
            offa[c + 1] = aa;
            offb[c + 1] = bb;
        }
    }
    __syncthreads();

    if (t < 16) {
        int j = j0 + t;
        float dj = g_d[j];
        float smax = g_smaxp[0];
        float x = -dj;
        int lo = 0, hi = 1024;
        while (lo < hi) {
            int mid = (lo + hi) >> 1;
            if (sorted_s[mid] <= x) lo = mid + 1; else hi = mid;
        }
        int k = lo;                 // count of s_i <= -d_j
        ks_s[t] = k;
        float tt = smax + dj;
        float mj = tt > 0.f ? tt : 0.2f * tt;
        float fB = __expf(tt - mj);
        float fA = __expf(0.2f * tt - mj);
        float av = 0.f, bv = 0.f;
        if (k > 0) {
            int p = k - 1;
            av = offa[p >> 6] + g_a[p];
            bv = offb[p >> 6] + g_b[p];
        }
        float btot = offb[16];
        float den = fA * av + fB * (btot - bv);
        fA_s[t] = fA;
        fB_s[t] = fB;
        inv_s[t] = 1.0f / den;
    }
    __syncthreads();

    const int ITER = 16 * D / 256;
#pragma unroll
    for (int it = 0; it < ITER; it++) {
        int o = t + it * 256;
        int jj = o / D, f = o % D;
        int k = ks_s[jj];
        float Av = 0.f, Bpre = 0.f;
        if (k > 0) {
            int p = k - 1;
            int ch = p >> 6;
            Av   = offA[ch * D + f] + g_A[(size_t)p * D + f];
            Bpre = offB[ch * D + f] + g_B[(size_t)p * D + f];
        }
        float Btot = offB[16 * D + f];
        float num = fA_s[jj] * Av + fB_s[jj] * (Btot - Bpre);
        float y = num * inv_s[jj] + bias[f];
        out[(size_t)(j0 + jj) * D + f] = y > 0.f ? y : 0.f;
    }
}

// ---------------- mean pool stage 1 ----------------
__global__ __launch_bounds__(128) void pool_partial_kernel()
{
    int b = blockIdx.x >> 3, ch = blockIdx.x & 7, t = threadIdx.x;
    const float* base = g_x2 + (b * 1024 + ch * 128) * 128;
    float acc = 0.f;
    for (int n = 0; n < 128; n++) acc += base[n * 128 + t];
    g_part[blockIdx.x * 128 + t] = acc;
}

// ---------------- stage 2: combine + linear + log_softmax ----------------
__global__ __launch_bounds__(128) void final_kernel(
    const float* __restrict__ W, const float* __restrict__ bo,
    float* __restrict__ out)
{
    __shared__ float meanv[128];
    __shared__ float logits[10];
    __shared__ float stats[2];
    int b = blockIdx.x;
    int t = threadIdx.x;
    float acc = 0.f;
#pragma unroll
    for (int k = 0; k < 8; k++) acc += g_part[(b * 8 + k) * 128 + t];
    meanv[t] = acc * (1.0f / 1024.0f);
    __syncthreads();
    if (t < 10) {
        float lg = bo[t];
        for (int f = 0; f < 128; f++) lg += meanv[f] * W[f * 10 + t];
        logits[t] = lg;
    }
    __syncthreads();
    if (t == 0) {
        float mv = -1e30f;
        for (int k = 0; k < 10; k++) mv = fmaxf(mv, logits[k]);
        float se = 0.f;
        for (int k = 0; k < 10; k++) se += expf(logits[k] - mv);
        stats[0] = mv;
        stats[1] = logf(se);
    }
    __syncthreads();
    if (t < 10) out[b * 10 + t] = logits[t] - stats[0] - stats[1];
}

// ---------------- launch ----------------
extern "C" void kernel_launch(void* const* d_in, const int* in_sizes, int n_in,
                              void* d_out, int out_size)
{
    const float* images  = (const float*)d_in[0];
    const float* conv1_w = (const float*)d_in[1];
    const float* conv1_b = (const float*)d_in[2];
    const float* bn1_g   = (const float*)d_in[3];
    const float* bn1_b   = (const float*)d_in[4];
    const float* bn1_m   = (const float*)d_in[5];
    const float* bn1_v   = (const float*)d_in[6];
    const float* conv2_w = (const float*)d_in[7];
    const float* conv2_b = (const float*)d_in[8];
    const float* bn2_g   = (const float*)d_in[9];
    const float* bn2_b   = (const float*)d_in[10];
    const float* bn2_m   = (const float*)d_in[11];
    const float* bn2_v   = (const float*)d_in[12];
    const float* gat1_w    = (const float*)d_in[13];
    const float* gat1_asrc = (const float*)d_in[14];
    const float* gat1_adst = (const float*)d_in[15];
    const float* gat1_bias = (const float*)d_in[16];
    const float* gat2_w    = (const float*)d_in[17];
    const float* gat2_asrc = (const float*)d_in[18];
    const float* gat2_adst = (const float*)d_in[19];
    const float* gat2_bias = (const float*)d_in[20];
    const float* out_w = (const float*)d_in[21];
    const float* out_b = (const float*)d_in[22];
    float* out = (float*)d_out;

    float* nodes0 = nullptr; cudaGetSymbolAddress((void**)&nodes0, g_nodes0);
    float* h1 = nullptr;     cudaGetSymbolAddress((void**)&h1, g_h1);
    float* x1 = nullptr;     cudaGetSymbolAddress((void**)&x1, g_x1);
    float* h2 = nullptr;     cudaGetSymbolAddress((void**)&h2, g_h2);
    float* x2 = nullptr;     cudaGetSymbolAddress((void**)&x2, g_x2);
    float* s1p = nullptr;    cudaGetSymbolAddress((void**)&s1p, g_s1p);
    float* d1p = nullptr;    cudaGetSymbolAddress((void**)&d1p, g_d1p);
    float* s2p = nullptr;    cudaGetSymbolAddress((void**)&s2p, g_s2p);
    float* d2p = nullptr;    cudaGetSymbolAddress((void**)&d2p, g_d2p);

    stage1_kernel<<<2048 + 288, 256>>>(images, conv1_w, conv1_b, bn1_g, bn1_b,
                                       bn1_m, bn1_v, conv2_w);
    conv2_kernel<<<dim3(16, 2, 8), 256>>>(conv2_b, bn2_g, bn2_b, bn2_m, bn2_v);

    // GAT layer 1
    sgemm_fused<<<dim3(4, 64), 256>>>(nodes0, gat1_w, gat1_bias, gat1_asrc,
                                      gat1_adst, h1, x1, s1p, d1p, 256, 128);
    sortprep_kernel<4><<<128, 256>>>(s1p, d1p);
    scan_kernel<256><<<dim3(16, 4), 64>>>(h1);
    attn_combine<256><<<64, 256>>>(gat1_bias, x1);

    // GAT layer 2
    sgemm_fused<<<dim3(2, 64), 256>>>(x1, gat2_w, gat2_bias, gat2_asrc,
                                      gat2_adst, h2, x2, s2p, d2p, 128, 256);
    sortprep_kernel<2><<<128, 256>>>(s2p, d2p);
    scan_kernel<128><<<dim3(16, 2), 64>>>(h2);
    attn_combine<128><<<64, 256>>>(gat2_bias, x2);

    pool_partial_kernel<<<64, 128>>>();
    final_kernel<<<8, 128>>>(out_w, out_b, out);
}